// round 17
// baseline (speedup 1.0000x reference)
#include <cuda_runtime.h>
#include <stdint.h>

typedef unsigned long long u64;

#define HID   256
#define HOR   30
#define NC    5
#define NROWS 32768
#define TILE  64
#define NTHR  256
#define RPP   16   // rows per pair
#define EPR   8    // epilogue rows per warp

#define OFF_WIN1 0
#define OFF_BIN1 1792
#define OFF_BIN2 2048
#define OFF_LN1G 2304
#define OFF_LN1B 2560
#define OFF_BIH  2816
#define OFF_BHH  3584
#define OFF_LN2G 4352
#define OFF_LN2B 4608
#define OFF_BM1  4864
#define OFF_WM2  4992
#define OFF_BM2  5632
#define OFF_DT   5640
#define OFF_FEAT 5652
#define CONSTF   6176
#define SMEM_BYTES ((3*TILE*HID + CONSTF)*4)   // 221312 -> 1 CTA/SM

#define GRP  16384
#define HGRP 8192   // half-k offset within a group (64 k2 * 128)

__device__ int g_cnt;
__device__ int g_fmt;
__device__ int g_active[NROWS];
__device__ u64 wih_p[6*GRP];
__device__ u64 whh_p[6*GRP];
__device__ u64 win2_p[2*GRP];
__device__ u64 wm1_p[1*GRP];

__device__ __forceinline__ void ffma2(u64 &d, u64 a, u64 b){
    asm("fma.rn.f32x2 %0, %1, %2, %0;" : "+l"(d) : "l"(a), "l"(b));
}
__device__ __forceinline__ void unpk(u64 v, float &lo, float &hi){
    unsigned a, b;
    asm("mov.b64 {%0, %1}, %2;" : "=r"(a), "=r"(b) : "l"(v));
    lo = __uint_as_float(a); hi = __uint_as_float(b);
}
__device__ __forceinline__ u64 pack2(float lo, float hi){
    u64 r;
    asm("mov.b64 %0, {%1, %2};" : "=l"(r) : "r"(__float_as_uint(lo)), "r"(__float_as_uint(hi)));
    return r;
}
__device__ __forceinline__ float mergef(u64 v){
    float lo, hi; unpk(v, lo, hi); return lo + hi;
}
__device__ __forceinline__ float wsum(float v){
    #pragma unroll
    for (int o = 16; o; o >>= 1) v += __shfl_xor_sync(0xffffffffu, v, o);
    return v;
}
__device__ __forceinline__ float sigf(float x){
    return __fdividef(1.0f, 1.0f + __expf(-x));
}
__device__ __forceinline__ float tanhf_(float x){
    return fmaf(2.0f, sigf(2.0f * x), -1.0f);
}
__device__ __forceinline__ void pbar(int barid){
    asm volatile("bar.sync %0, 64;" :: "r"(barid) : "memory");
}

__global__ void k_detect(const unsigned* __restrict__ m){
    __shared__ int f8, ff;
    if (threadIdx.x == 0){ f8 = 0; ff = 0; g_cnt = 0; }
    __syncthreads();
    int a = 0, b = 0;
    for (int i = threadIdx.x; i < 8192; i += 256){
        unsigned w = m[i];
        if (w == 0x3F800000u) b = 1;
        else if (w > 1u)      a = 1;
    }
    if (a) atomicOr(&f8, 1);
    if (b) atomicOr(&ff, 1);
    __syncthreads();
    if (threadIdx.x == 0) g_fmt = ff ? 2 : (f8 ? 0 : 1);
}

__global__ void k_compact(const void* __restrict__ mask, int n){
    int i = blockIdx.x * blockDim.x + threadIdx.x;
    if (i >= n) return;
    int fmt = g_fmt;
    bool m;
    if (fmt == 0)      m = ((const unsigned char*)mask)[i] != 0;
    else if (fmt == 1) m = ((const int*)mask)[i] != 0;
    else               m = ((const float*)mask)[i] != 0.0f;
    if (m) g_active[atomicAdd(&g_cnt, 1)] = i;
}

__device__ __forceinline__ void pack_one(u64* dst, const float* w, int C, int i){
    int g    = i / GRP;
    int rem  = i % GRP;
    int k2   = rem / 128;
    int rem2 = rem % 128;
    int h    = rem2 / 64;
    int l2   = rem2 % 64;
    int lane = l2 / 2;
    int j    = l2 % 2;
    int col  = g*128 + 4*lane + 2*h + j;
    dst[i] = pack2(w[(2*k2)*C + col], w[(2*k2+1)*C + col]);
}

__global__ void k_packzero(float4* __restrict__ p, int n4,
                           const float* __restrict__ wih, const float* __restrict__ whh,
                           const float* __restrict__ win2, const float* __restrict__ wm1){
    int i = blockIdx.x * blockDim.x + threadIdx.x;
    if (i < n4) p[i] = make_float4(0.f, 0.f, 0.f, 0.f);
    if (i < 6*GRP){
        pack_one(wih_p, wih, 768, i);
        pack_one(whh_p, whh, 768, i);
    }
    if (i < 2*GRP) pack_one(win2_p, win2, 256, i);
    if (i < 1*GRP) pack_one(wm1_p,  wm1,  128, i);
}

// ---- K-split GEMM: 16 rows x 4 cols over HALF of k (128 k = 32 blocks) ----
__device__ __forceinline__ void ldw(ulonglong2 w[4], const u64* __restrict__ p){
    w[0] = *(const ulonglong2*)(p);
    w[1] = *(const ulonglong2*)(p + 64);
    w[2] = *(const ulonglong2*)(p + 128);
    w[3] = *(const ulonglong2*)(p + 192);
}
__device__ __forceinline__ void fmas16(u64 acc[RPP][4], const ulonglong2 w[4],
                                       const float* __restrict__ ap){
    #pragma unroll
    for (int r = 0; r < RPP; ++r){
        ulonglong2 av = *(const ulonglong2*)(ap + r*HID);
        ffma2(acc[r][0], av.x, w[0].x); ffma2(acc[r][1], av.x, w[0].y);
        ffma2(acc[r][2], av.x, w[1].x); ffma2(acc[r][3], av.x, w[1].y);
        ffma2(acc[r][0], av.y, w[2].x); ffma2(acc[r][1], av.y, w[2].y);
        ffma2(acc[r][2], av.y, w[3].x); ffma2(acc[r][3], av.y, w[3].y);
    }
}
__device__ __forceinline__ void gemmks(u64 acc[RPP][4], const float* __restrict__ act,
                                       const u64* __restrict__ wpl){
    ulonglong2 w0[4], w1[4];
    ldw(w0, wpl);
    const u64* p = wpl;
    const float* ap = act;
    #pragma unroll 1
    for (int it = 0; it < 15; ++it){
        ldw(w1, p + 256); fmas16(acc, w0, ap);
        ldw(w0, p + 512); fmas16(acc, w1, ap + 4);
        p += 512; ap += 8;
    }
    ldw(w1, p + 256);
    fmas16(acc, w0, ap);        // block 30
    fmas16(acc, w1, ap + 4);    // block 31
}

__device__ __forceinline__ void initb(u64 acc[RPP][4], const float* __restrict__ b){
    u64 p[4];
    #pragma unroll
    for (int j = 0; j < 4; ++j) p[j] = (u64)__float_as_uint(b[j]);
    #pragma unroll
    for (int r = 0; r < RPP; ++r)
        #pragma unroll
        for (int j = 0; j < 4; ++j) acc[r][j] = p[j];
}
__device__ __forceinline__ void initb2(u64 acc[RPP][4], const float* __restrict__ b1,
                                       const float* __restrict__ b2){
    u64 p[4];
    #pragma unroll
    for (int j = 0; j < 4; ++j) p[j] = (u64)__float_as_uint(b1[j] + b2[j]);
    #pragma unroll
    for (int r = 0; r < RPP; ++r)
        #pragma unroll
        for (int j = 0; j < 4; ++j) acc[r][j] = p[j];
}

// merge partials across the warp pair; result = full sums for my EPR rows.
// scr = pair-row base of a free smem buffer; cabs = absolute col of lane's 4 cols.
__device__ __forceinline__ void merge8(float full[EPR][4], const u64 acc[RPP][4],
                                       float* __restrict__ scr, int kh, int cabs, int barid){
    pbar(barid);   // WAR: partner finished reading previous use of scr region
    #pragma unroll
    for (int r = 0; r < EPR; ++r){
        int rr = (1-kh)*EPR + r;
        *(float4*)(scr + rr*HID + cabs) =
            make_float4(mergef(acc[rr][0]), mergef(acc[rr][1]),
                        mergef(acc[rr][2]), mergef(acc[rr][3]));
    }
    pbar(barid);
    #pragma unroll
    for (int r = 0; r < EPR; ++r){
        int rr = kh*EPR + r;
        float4 v = *(float4*)(scr + rr*HID + cabs);
        full[r][0] = v.x + mergef(acc[rr][0]);
        full[r][1] = v.y + mergef(acc[rr][1]);
        full[r][2] = v.z + mergef(acc[rr][2]);
        full[r][3] = v.w + mergef(acc[rr][3]);
    }
}

__device__ __forceinline__ void cpyf(float* dst, const float* src, int n, int tid){
    for (int i = tid; i < n; i += NTHR) dst[i] = src[i];
}

// input_proj: h1 (my rows) -> xP; win2 gemm (k-split, merged); LN+relu -> xP
__device__ __forceinline__ void ipro(const float* __restrict__ feats,
        const float* __restrict__ sc, const u64* __restrict__ win2L,
        float* __restrict__ xP, float* __restrict__ scrP,
        int kh, int c0, int barid){
    #pragma unroll
    for (int r = 0; r < EPR; ++r){
        int row = kh*EPR + r;
        float h[8];
        #pragma unroll
        for (int j = 0; j < 8; ++j){
            int c = c0 + (j < 4 ? j : 124 + j);
            float s = sc[OFF_BIN1 + c];
            #pragma unroll
            for (int k = 0; k < 7; ++k)
                s = fmaf(feats[r*8 + k], sc[OFF_WIN1 + k*HID + c], s);
            h[j] = fmaxf(s, 0.f);
        }
        *(float4*)(xP + row*HID + c0)       = make_float4(h[0], h[1], h[2], h[3]);
        *(float4*)(xP + row*HID + c0 + 128) = make_float4(h[4], h[5], h[6], h[7]);
    }
    pbar(barid);   // both halves of x(h1) visible
    float s8[EPR], q8[EPR];
    #pragma unroll
    for (int r = 0; r < EPR; ++r){ s8[r] = 0.f; q8[r] = 0.f; }
    #pragma unroll 1
    for (int cg = 0; cg < 2; ++cg){
        int cb = cg*128 + c0;
        u64 acc[RPP][4];
        initb(acc, sc + OFF_BIN2 + cb);
        gemmks(acc, xP + kh*128, win2L + cg*GRP + kh*HGRP);
        float full[EPR][4];
        merge8(full, acc, scrP, kh, cb, barid);
        #pragma unroll
        for (int r = 0; r < EPR; ++r){
            int row = kh*EPR + r;
            *(float4*)(scrP + row*HID + cb) =
                make_float4(full[r][0], full[r][1], full[r][2], full[r][3]);
            s8[r] += full[r][0] + full[r][1] + full[r][2] + full[r][3];
            q8[r] = fmaf(full[r][0], full[r][0], fmaf(full[r][1], full[r][1],
                    fmaf(full[r][2], full[r][2], fmaf(full[r][3], full[r][3], q8[r]))));
        }
    }
    #pragma unroll
    for (int r = 0; r < EPR; ++r){
        int row = kh*EPR + r;
        float mu = wsum(s8[r]) * (1.0f/256.0f);
        float var = wsum(q8[r]) * (1.0f/256.0f) - mu*mu;
        float iv = rsqrtf(var + 1e-5f);
        #pragma unroll
        for (int half = 0; half < 2; ++half){
            int c = c0 + half*128;
            float4 v = *(float4*)(scrP + row*HID + c);
            float4 o;
            o.x = fmaxf((v.x - mu)*iv*sc[OFF_LN1G+c]   + sc[OFF_LN1B+c],   0.f);
            o.y = fmaxf((v.y - mu)*iv*sc[OFF_LN1G+c+1] + sc[OFF_LN1B+c+1], 0.f);
            o.z = fmaxf((v.z - mu)*iv*sc[OFF_LN1G+c+2] + sc[OFF_LN1B+c+2], 0.f);
            o.w = fmaxf((v.w - mu)*iv*sc[OFF_LN1G+c+3] + sc[OFF_LN1B+c+3], 0.f);
            *(float4*)(xP + row*HID + c) = o;
        }
    }
    pbar(barid);   // x fully LN'd before gate gemms read it
}

// ---- main kernel: 256 thr, 8 warps = 4 pairs x 2 k-halves, RPP=16, 1 CTA/SM ----
__global__ void __launch_bounds__(NTHR, 1)
k_main(const float* __restrict__ obs,
       const float* __restrict__ delta_table,
       const float* __restrict__ w_in1, const float* __restrict__ b_in1,
       const float* __restrict__ b_in2,
       const float* __restrict__ ln1g, const float* __restrict__ ln1b,
       const float* __restrict__ b_ih, const float* __restrict__ b_hh,
       const float* __restrict__ ln2g, const float* __restrict__ ln2b,
       const float* __restrict__ b_m1,
       const float* __restrict__ w_m2, const float* __restrict__ b_m2,
       float* __restrict__ out)
{
    int cnt = g_cnt;
    int base = blockIdx.x * TILE;
    if (base >= cnt) return;

    extern __shared__ float smemf[];
    float* xd = smemf;
    float* hP = smemf + TILE*HID;
    float* hQ = smemf + 2*TILE*HID;
    float* sc = smemf + 3*TILE*HID;

    int tid = threadIdx.x;
    cpyf(sc + OFF_WIN1, w_in1, 7*HID, tid);
    cpyf(sc + OFF_BIN1, b_in1, HID, tid);
    cpyf(sc + OFF_BIN2, b_in2, HID, tid);
    cpyf(sc + OFF_LN1G, ln1g, HID, tid);
    cpyf(sc + OFF_LN1B, ln1b, HID, tid);
    cpyf(sc + OFF_BIH,  b_ih, 3*HID, tid);
    cpyf(sc + OFF_BHH,  b_hh, 3*HID, tid);
    cpyf(sc + OFF_LN2G, ln2g, HID, tid);
    cpyf(sc + OFF_LN2B, ln2b, HID, tid);
    cpyf(sc + OFF_BM1,  b_m1, 128, tid);
    cpyf(sc + OFF_WM2,  w_m2, 640, tid);
    cpyf(sc + OFF_BM2,  b_m2, NC, tid);
    cpyf(sc + OFF_DT,   delta_table, NC*2, tid);
    __syncthreads();

    int lane = tid & 31, warp = tid >> 5;
    int pair = warp >> 1, kh = warp & 1;
    int R0 = pair * RPP;                 // pair's first row in tile
    int barid = 1 + pair;
    if (base + R0 >= cnt) return;        // pair-uniform exit

    int myrow0 = R0 + kh*EPR;            // my epilogue rows (global tile-relative)
    int gi[EPR]; bool valid[EPR];
    #pragma unroll
    for (int r = 0; r < EPR; ++r){
        int idx = base + myrow0 + r;
        valid[r] = (idx < cnt);
        gi[r] = g_active[valid[r] ? idx : base];
    }

    float* feats = sc + OFF_FEAT + myrow0*8;
    #pragma unroll
    for (int r = 0; r < EPR; ++r){
        if (lane < 7) feats[r*8 + lane] = obs[(size_t)gi[r]*7 + lane];
    }
    __syncwarp();

    const int c0 = lane * 4;
    float* xP = xd + R0*HID;             // pair-row bases
    float* hAP = hP + R0*HID;
    float* hBP = hQ + R0*HID;
    const float* dt = sc + OFF_DT;
    const u64* wihL  = wih_p  + 2*lane;
    const u64* whhL  = whh_p  + 2*lane;
    const u64* win2L = win2_p + 2*lane;
    const u64* wm1L  = wm1_p  + 2*lane;

    // h0 = x0 (my rows), then pair barrier
    ipro(feats, sc, win2L, xP, hBP, kh, c0, barid);
    #pragma unroll
    for (int r = 0; r < EPR; ++r){
        int row = kh*EPR + r;
        *(float4*)(hAP + row*HID + c0)       = *(float4*)(xP + row*HID + c0);
        *(float4*)(hAP + row*HID + c0 + 128) = *(float4*)(xP + row*HID + c0 + 128);
    }
    pbar(barid);

    float* hcurP = hAP;
    float* hnxtP = hBP;

    for (int t = 0; t < HOR; ++t){
        if (t > 0) ipro(feats, sc, win2L, xP, hnxtP, kh, c0, barid);

        float s8[EPR], q8[EPR];
        #pragma unroll
        for (int r = 0; r < EPR; ++r){ s8[r] = 0.f; q8[r] = 0.f; }

        #pragma unroll 1
        for (int cg = 0; cg < 2; ++cg){
            int cb = cg*128 + c0;
            u64 acc[RPP][4];
            // r gate
            initb2(acc, sc + OFF_BIH + cb, sc + OFF_BHH + cb);
            gemmks(acc, xP + kh*128,   wihL + (0 + cg)*GRP + kh*HGRP);
            gemmks(acc, hcurP + kh*128, whhL + (0 + cg)*GRP + kh*HGRP);
            float rr8[EPR][4];
            merge8(rr8, acc, hnxtP, kh, cb, barid);
            #pragma unroll
            for (int r = 0; r < EPR; ++r)
                #pragma unroll
                for (int j = 0; j < 4; ++j) rr8[r][j] = sigf(rr8[r][j]);
            // hn -> rhn (into rr8)
            initb(acc, sc + OFF_BHH + 512 + cb);
            gemmks(acc, hcurP + kh*128, whhL + (4 + cg)*GRP + kh*HGRP);
            {
                float hn8[EPR][4];
                merge8(hn8, acc, hnxtP, kh, cb, barid);
                #pragma unroll
                for (int r = 0; r < EPR; ++r)
                    #pragma unroll
                    for (int j = 0; j < 4; ++j) rr8[r][j] *= hn8[r][j];
            }
            // inn -> n (into rr8)
            initb(acc, sc + OFF_BIH + 512 + cb);
            gemmks(acc, xP + kh*128, wihL + (4 + cg)*GRP + kh*HGRP);
            {
                float in8[EPR][4];
                merge8(in8, acc, hnxtP, kh, cb, barid);
                #pragma unroll
                for (int r = 0; r < EPR; ++r)
                    #pragma unroll
                    for (int j = 0; j < 4; ++j) rr8[r][j] = tanhf_(in8[r][j] + rr8[r][j]);
            }
            // z gate + combine -> hnxt (pre-LN)
            initb2(acc, sc + OFF_BIH + 256 + cb, sc + OFF_BHH + 256 + cb);
            gemmks(acc, xP + kh*128,   wihL + (2 + cg)*GRP + kh*HGRP);
            gemmks(acc, hcurP + kh*128, whhL + (2 + cg)*GRP + kh*HGRP);
            {
                float zz8[EPR][4];
                merge8(zz8, acc, hnxtP, kh, cb, barid);
                #pragma unroll
                for (int r = 0; r < EPR; ++r){
                    int row = kh*EPR + r;
                    float4 hv = *(float4*)(hcurP + row*HID + cb);
                    float v0 = (1.0f - sigf(zz8[r][0])) * rr8[r][0] + sigf(zz8[r][0]) * hv.x;
                    float v1 = (1.0f - sigf(zz8[r][1])) * rr8[r][1] + sigf(zz8[r][1]) * hv.y;
                    float v2 = (1.0f - sigf(zz8[r][2])) * rr8[r][2] + sigf(zz8[r][2]) * hv.z;
                    float v3 = (1.0f - sigf(zz8[r][3])) * rr8[r][3] + sigf(zz8[r][3]) * hv.w;
                    *(float4*)(hnxtP + row*HID + cb) = make_float4(v0, v1, v2, v3);
                    s8[r] += v0 + v1 + v2 + v3;
                    q8[r] = fmaf(v0, v0, fmaf(v1, v1, fmaf(v2, v2, fmaf(v3, v3, q8[r]))));
                }
            }
        }
        // LayerNorm2 on my rows of hnxt
        #pragma unroll
        for (int r = 0; r < EPR; ++r){
            int row = kh*EPR + r;
            float mu = wsum(s8[r]) * (1.0f/256.0f);
            float var = wsum(q8[r]) * (1.0f/256.0f) - mu*mu;
            float iv = rsqrtf(var + 1e-5f);
            #pragma unroll
            for (int half = 0; half < 2; ++half){
                int c = c0 + half*128;
                float4 v = *(float4*)(hnxtP + row*HID + c);
                float4 o;
                o.x = (v.x - mu)*iv*sc[OFF_LN2G+c]   + sc[OFF_LN2B+c];
                o.y = (v.y - mu)*iv*sc[OFF_LN2G+c+1] + sc[OFF_LN2B+c+1];
                o.z = (v.z - mu)*iv*sc[OFF_LN2G+c+2] + sc[OFF_LN2B+c+2];
                o.w = (v.w - mu)*iv*sc[OFF_LN2G+c+3] + sc[OFF_LN2B+c+3];
                *(float4*)(hnxtP + row*HID + c) = o;
            }
        }
        pbar(barid);   // both halves of new h complete before mh gemm

        // move head layer 1 (128 cols); merge scratch = xd (x is dead now)
        u64 am[RPP][4];
        initb(am, sc + OFF_BM1 + c0);
        gemmks(am, hnxtP + kh*128, wm1L + kh*HGRP);
        float mv[EPR][4];
        merge8(mv, am, xP, kh, c0, barid);
        #pragma unroll
        for (int r = 0; r < EPR; ++r)
            #pragma unroll
            for (int j = 0; j < 4; ++j) mv[r][j] = fmaxf(mv[r][j], 0.f);

        // logits (warp reduce over 128 cols) for my rows
        float part[EPR][NC];
        #pragma unroll
        for (int r = 0; r < EPR; ++r)
            #pragma unroll
            for (int c = 0; c < NC; ++c) part[r][c] = 0.f;
        #pragma unroll
        for (int r = 0; r < EPR; ++r)
            #pragma unroll
            for (int j = 0; j < 4; ++j)
                #pragma unroll
                for (int c = 0; c < NC; ++c)
                    part[r][c] = fmaf(mv[r][j], sc[OFF_WM2 + (c0 + j)*NC + c], part[r][c]);
        #pragma unroll
        for (int off = 16; off; off >>= 1)
            #pragma unroll
            for (int r = 0; r < EPR; ++r)
                #pragma unroll
                for (int c = 0; c < NC; ++c)
                    part[r][c] += __shfl_xor_sync(0xffffffffu, part[r][c], off);
        #pragma unroll
        for (int r = 0; r < EPR; ++r)
            #pragma unroll
            for (int c = 0; c < NC; ++c) part[r][c] += sc[OFF_BM2 + c];

        #pragma unroll
        for (int r = 0; r < EPR; ++r){
            if (lane < NC && valid[r]){
                float vv = (lane == 0) ? part[r][0] :
                           (lane == 1) ? part[r][1] :
                           (lane == 2) ? part[r][2] :
                           (lane == 3) ? part[r][3] : part[r][4];
                out[(size_t)gi[r]*(HOR*NC) + t*NC + lane] = vv;
            }
        }

        if (t + 1 < HOR){
            #pragma unroll
            for (int r = 0; r < EPR; ++r){
                float m = part[r][0];
                #pragma unroll
                for (int c = 1; c < NC; ++c) m = fmaxf(m, part[r][c]);
                float e[NC], s = 0.f;
                #pragma unroll
                for (int c = 0; c < NC; ++c){ e[c] = __expf(part[r][c] - m); s += e[c]; }
                float inv = __fdividef(1.0f, s);
                float dx = 0.f, dy = 0.f;
                #pragma unroll
                for (int c = 0; c < NC; ++c){
                    dx = fmaf(e[c], dt[2*c],   dx);
                    dy = fmaf(e[c], dt[2*c+1], dy);
                }
                dx *= inv; dy *= inv;
                if (lane == 0){
                    feats[r*8+0] = fminf(fmaxf(feats[r*8+0] + dx, 0.f), 1.f);
                    feats[r*8+1] = fminf(fmaxf(feats[r*8+1] + dy, 0.f), 1.f);
                }
            }
            __syncwarp();
        }

        float* tmp = hcurP; hcurP = hnxtP; hnxtP = tmp;
    }
}

extern "C" void kernel_launch(void* const* d_in, const int* in_sizes, int n_in,
                              void* d_out, int out_size) {
    const float* obs  = (const float*)d_in[0];
    const void*  mask = d_in[1];
    const float* dt   = (const float*)d_in[2];
    const float* w_in1 = (const float*)d_in[3];
    const float* b_in1 = (const float*)d_in[4];
    const float* w_in2 = (const float*)d_in[5];
    const float* b_in2 = (const float*)d_in[6];
    const float* ln1g  = (const float*)d_in[7];
    const float* ln1b  = (const float*)d_in[8];
    const float* w_ih  = (const float*)d_in[9];
    const float* b_ih  = (const float*)d_in[10];
    const float* w_hh  = (const float*)d_in[11];
    const float* b_hh  = (const float*)d_in[12];
    const float* ln2g  = (const float*)d_in[13];
    const float* ln2b  = (const float*)d_in[14];
    const float* w_m1  = (const float*)d_in[15];
    const float* b_m1  = (const float*)d_in[16];
    const float* w_m2  = (const float*)d_in[17];
    const float* b_m2  = (const float*)d_in[18];
    float* out = (float*)d_out;

    static int attr_set = 0;
    if (!attr_set){
        cudaFuncSetAttribute(k_main, cudaFuncAttributeMaxDynamicSharedMemorySize, SMEM_BYTES);
        attr_set = 1;
    }

    k_detect<<<1, 256>>>((const unsigned*)mask);
    k_compact<<<(NROWS + 255)/256, 256>>>(mask, NROWS);
    k_packzero<<<(out_size/4 + 255)/256, 256>>>((float4*)out, out_size/4,
                                                w_ih, w_hh, w_in2, w_m1);
    k_main<<<NROWS/TILE, NTHR, SMEM_BYTES>>>(
        obs, dt, w_in1, b_in1, b_in2, ln1g, ln1b,
        b_ih, b_hh, ln2g, ln2b, b_m1, w_m2, b_m2, out);
}